// round 9
// baseline (speedup 1.0000x reference)
#include <cuda_runtime.h>
#include <cuda_fp16.h>
#include <cstdint>

#define NROWS 32768
#define D 256
#define K 4096
#define DECAY 0.99f
#define ONE_MINUS_DECAY 0.01f
#define EPSV 1e-5f
#define COMMIT 0.25f
#define SX 21.0f
#define SE 1024.0f

static const size_t OFF_Q    = 0;
static const size_t OFF_LOSS = 8388608;
static const size_t OFF_PERP = 8388609;
static const size_t OFF_IDX  = 8388610;
static const size_t OFF_NE   = 8421378;

// -------- device scratch --------
__device__ float g_ce[K];
__device__ float g_ET[(size_t)K * D];
__device__ __align__(16) int8_t g_xq[(size_t)NROWS * D];
__device__ __align__(16) int8_t g_eq[(size_t)K * D];
__device__ float g_dw[(size_t)D * K];             // [d][k]
__device__ int   g_counts[K];
__device__ float4 g_t2[(size_t)NROWS * 32];       // [row][cg] = {v1, i1, v2, i2}
__device__ float g_loss;
__device__ float g_bias;
__device__ float g_cnorm[K];

// ================= PTX helpers =================
__device__ __forceinline__ uint32_t smem_to_u32(const void* p) {
    uint32_t a;
    asm("{ .reg .u64 t; cvta.to.shared.u64 t, %1; cvt.u32.u64 %0, t; }" : "=r"(a) : "l"(p));
    return a;
}
__device__ __forceinline__ void cp16(uint32_t saddr, const void* g) {
    asm volatile("cp.async.cg.shared.global [%0], [%1], 16;" :: "r"(saddr), "l"(g));
}
#define CP_COMMIT() asm volatile("cp.async.commit_group;" ::: "memory")

#define LDSM4(r0, r1, r2, r3, a) \
    asm volatile("ldmatrix.sync.aligned.m8n8.x4.shared.b16 {%0,%1,%2,%3}, [%4];" \
        : "=r"(r0), "=r"(r1), "=r"(r2), "=r"(r3) : "r"(a))
#define LDSM2(r0, r1, a) \
    asm volatile("ldmatrix.sync.aligned.m8n8.x2.shared.b16 {%0,%1}, [%2];" \
        : "=r"(r0), "=r"(r1) : "r"(a))

__device__ __forceinline__ void imma16832(int* c, const uint32_t* a, const uint32_t* b) {
    asm volatile("mma.sync.aligned.m16n8k32.row.col.s32.s8.s8.s32 "
        "{%0,%1,%2,%3}, {%4,%5,%6,%7}, {%8,%9}, {%0,%1,%2,%3};"
        : "+r"(c[0]), "+r"(c[1]), "+r"(c[2]), "+r"(c[3])
        : "r"(a[0]), "r"(a[1]), "r"(a[2]), "r"(a[3]), "r"(b[0]), "r"(b[1]));
}

__device__ __forceinline__ uint32_t sw128(uint32_t b) { return b ^ ((b >> 3) & 0x70); }
__device__ __forceinline__ bool lt2(float v, int i, float u, int j) {
    return v < u || (v == u && i < j);
}
__device__ __forceinline__ int8_t q8(float v, float s) {
    int r = __float2int_rn(v * s);
    r = r > 127 ? 127 : (r < -127 ? -127 : r);
    return (int8_t)r;
}

// ================= small kernels =================
__global__ void k_zero() {
    int i = blockIdx.x * blockDim.x + threadIdx.x, st = gridDim.x * blockDim.x;
    for (int j = i; j < D * K; j += st) g_dw[j] = 0.f;
    for (int j = i; j < K; j += st) g_counts[j] = 0;
    if (i == 0) g_loss = 0.f;
}

__global__ void k_ce(const float* __restrict__ E) {
    int k = blockIdx.x * 256 + threadIdx.x;
    float s = 0.f;
    #pragma unroll 8
    for (int d = 0; d < D; d++) { float v = E[(size_t)d * K + k]; s = fmaf(v, v, s); }
    g_ce[k] = s;
}

// transpose E -> g_ET (fp32) and g_eq (int8) in one pass
__global__ void k_transpose(const float* __restrict__ E) {
    __shared__ float t[32][33];
    int kb = blockIdx.x * 32, db = blockIdx.y * 32;
    int x = threadIdx.x, y0 = threadIdx.y;
    #pragma unroll
    for (int j = 0; j < 32; j += 8) t[y0 + j][x] = E[(size_t)(db + y0 + j) * K + kb + x];
    __syncthreads();
    #pragma unroll
    for (int j = 0; j < 32; j += 8) {
        float v = t[x][y0 + j];
        size_t o = (size_t)(kb + y0 + j) * D + db + x;
        g_ET[o] = v;
        g_eq[o] = q8(v, SE);
    }
}

__global__ void k_xq(const float* __restrict__ X) {
    size_t i = (size_t)blockIdx.x * 256 + threadIdx.x;
    float4 a = *(const float4*)(X + i * 8);
    float4 b = *(const float4*)(X + i * 8 + 4);
    int8_t h[8] = { q8(a.x,SX), q8(a.y,SX), q8(a.z,SX), q8(a.w,SX),
                    q8(b.x,SX), q8(b.y,SX), q8(b.z,SX), q8(b.w,SX) };
    *(uint2*)(g_xq + i * 8) = *(uint2*)h;
}

// ================= approx argmin GEMM (IMMA s8, K=256, top-2 per 128-tile) =================
// 2 stages of k=128 bytes; A 16KB + B 16KB per stage; scores reuse buffer smem.
#define ST_SZ   32768
#define SM_CS   66048
#define SMEM_SZ 66560

__global__ void __launch_bounds__(256, 2)
k_argmin() {
    extern __shared__ char smem[];
    const int tid = threadIdx.x;
    const int wid = tid >> 5, lane = tid & 31;
    const int rt = blockIdx.x >> 5, cg = blockIdx.x & 31;
    const int row0 = rt * 128, kc0 = cg * 128;
    const int wr = wid >> 2, wc = wid & 3;
    const uint32_t sb = smem_to_u32(smem);
    const float SC2 = 2.0f / (SX * SE);

    float* cs = (float*)(smem + SM_CS);
    if (tid < 128) cs[tid] = g_ce[kc0 + tid];

    const int8_t* Ag = g_xq + (size_t)row0 * D;
    const int8_t* Bg = g_eq + (size_t)kc0 * D;

    int acc[4][4][4];
    #pragma unroll
    for (int mt = 0; mt < 4; mt++)
        #pragma unroll
        for (int nt = 0; nt < 4; nt++)
            #pragma unroll
            for (int j = 0; j < 4; j++) acc[mt][nt][j] = 0;

    auto issue = [&](int st) {
        uint32_t abase = sb + (uint32_t)st * ST_SZ;
        uint32_t bbase = abase + 16384;
        int k0 = st * 128;                         // byte offset within 256B row
        #pragma unroll
        for (int j = 0; j < 4; j++) {
            int chunk = tid + j * 256;
            int r = chunk >> 3, cc = chunk & 7;
            uint32_t so = sw128((uint32_t)(r * 128 + cc * 16));
            cp16(abase + so, Ag + (size_t)r * D + k0 + cc * 16);
            cp16(bbase + so, Bg + (size_t)r * D + k0 + cc * 16);
        }
        CP_COMMIT();
    };

    issue(0); issue(1);

    const int l15 = lane & 15;

    #pragma unroll
    for (int st = 0; st < 2; st++) {
        if (st == 0) asm volatile("cp.async.wait_group 1;" ::: "memory");
        else         asm volatile("cp.async.wait_group 0;" ::: "memory");
        __syncthreads();
        uint32_t abase = sb + (uint32_t)st * ST_SZ;
        uint32_t bbase = abase + 16384;

        #pragma unroll
        for (int s = 0; s < 4; s++) {              // each s-step = 32 int8 k-values
            uint32_t af[4][4], bf[4][2];
            #pragma unroll
            for (int mt = 0; mt < 4; mt++) {
                uint32_t ro = sw128((uint32_t)((wr * 64 + mt * 16 + l15) * 128 + s * 32 + (lane >> 4) * 16));
                LDSM4(af[mt][0], af[mt][1], af[mt][2], af[mt][3], abase + ro);
            }
            #pragma unroll
            for (int nt = 0; nt < 4; nt++) {
                uint32_t ro = sw128((uint32_t)((wc * 32 + nt * 8 + (l15 & 7)) * 128 + s * 32 + ((l15 >> 3) & 1) * 16));
                LDSM2(bf[nt][0], bf[nt][1], bbase + ro);
            }
            #pragma unroll
            for (int mt = 0; mt < 4; mt++)
                #pragma unroll
                for (int nt = 0; nt < 4; nt++)
                    imma16832(acc[mt][nt], af[mt], bf[nt]);
        }
        __syncthreads();
    }

    // ---- scores -> smem (stride 129 to kill bank conflicts; reuses tile buffers) ----
    float* sc = (float*)smem;
    #pragma unroll
    for (int mt = 0; mt < 4; mt++)
        #pragma unroll
        for (int h = 0; h < 2; h++) {
            int row = wr * 64 + mt * 16 + (lane >> 2) + 8 * h;
            #pragma unroll
            for (int nt = 0; nt < 4; nt++) {
                int col = wc * 32 + nt * 8 + 2 * (lane & 3);
                sc[row * 129 + col]     = cs[col]     - SC2 * (float)acc[mt][nt][h * 2 + 0];
                sc[row * 129 + col + 1] = cs[col + 1] - SC2 * (float)acc[mt][nt][h * 2 + 1];
            }
        }
    __syncthreads();

    // ---- per-row top-2 scan (1 thread/row; tie -> smaller index via strict <) ----
    if (tid < 128) {
        float v1 = 3.4e38f, v2 = 3.4e38f; int i1 = 0, i2 = 0;
        #pragma unroll 8
        for (int c = 0; c < 128; c++) {
            float v = sc[tid * 129 + c];
            if (v < v1) { v2 = v1; i2 = i1; v1 = v; i1 = c; }
            else if (v < v2) { v2 = v; i2 = c; }
        }
        g_t2[(size_t)(row0 + tid) * 32 + cg] =
            make_float4(v1, __int_as_float(kc0 + i1), v2, __int_as_float(kc0 + i2));
    }
}

// ================= select (top-4 merge + exact rescore) + scatter =================
__global__ void __launch_bounds__(256)
k_select(const float* __restrict__ X, float* __restrict__ out_q, float* __restrict__ out_idx) {
    const int wid = threadIdx.x >> 5, lane = threadIdx.x & 31;
    const size_t n = (size_t)blockIdx.x * 8 + wid;

    float4 cc = g_t2[n * 32 + lane];
    float t4v[4]; int t4i[4];
    t4v[0] = cc.x; t4i[0] = __float_as_int(cc.y);
    t4v[1] = cc.z; t4i[1] = __float_as_int(cc.w);
    t4v[2] = t4v[3] = 3.4e38f; t4i[2] = t4i[3] = 0x7fffffff;

    #pragma unroll
    for (int o = 1; o < 32; o <<= 1) {
        float rv[4]; int ri[4];
        #pragma unroll
        for (int s = 0; s < 4; s++) {
            rv[s] = __shfl_xor_sync(0xffffffffu, t4v[s], o);
            ri[s] = __shfl_xor_sync(0xffffffffu, t4i[s], o);
        }
        #pragma unroll
        for (int s = 0; s < 4; s++) {
            float v = rv[s]; int i = ri[s];
            if (lt2(v, i, t4v[3], t4i[3])) {
                if (lt2(v, i, t4v[0], t4i[0])) {
                    t4v[3]=t4v[2]; t4i[3]=t4i[2]; t4v[2]=t4v[1]; t4i[2]=t4i[1];
                    t4v[1]=t4v[0]; t4i[1]=t4i[0]; t4v[0]=v; t4i[0]=i;
                } else if (lt2(v, i, t4v[1], t4i[1])) {
                    t4v[3]=t4v[2]; t4i[3]=t4i[2]; t4v[2]=t4v[1]; t4i[2]=t4i[1];
                    t4v[1]=v; t4i[1]=i;
                } else if (lt2(v, i, t4v[2], t4i[2])) {
                    t4v[3]=t4v[2]; t4i[3]=t4i[2]; t4v[2]=v; t4i[2]=i;
                } else {
                    t4v[3]=v; t4i[3]=i;
                }
            }
        }
    }

    // exact fp32 rescore of 4 candidates
    const float4* xr = (const float4*)(X + n * D);
    float4 xa = xr[lane * 2], xb = xr[lane * 2 + 1];
    float bs = 3.4e38f; int bk = 0x7fffffff;
    #pragma unroll 1
    for (int c = 0; c < 4; c++) {
        int k = t4i[c];
        const float4* er = (const float4*)(g_ET + (size_t)k * D);
        float4 ea = er[lane * 2], eb = er[lane * 2 + 1];
        float d = xa.x*ea.x + xa.y*ea.y + xa.z*ea.z + xa.w*ea.w
                + xb.x*eb.x + xb.y*eb.y + xb.z*eb.z + xb.w*eb.w;
        float q = ea.x*ea.x + ea.y*ea.y + ea.z*ea.z + ea.w*ea.w
                + eb.x*eb.x + eb.y*eb.y + eb.z*eb.z + eb.w*eb.w;
        #pragma unroll
        for (int o = 16; o; o >>= 1) {
            d += __shfl_xor_sync(0xffffffffu, d, o);
            q += __shfl_xor_sync(0xffffffffu, q, o);
        }
        float s = q - 2.0f * d;
        if (s < bs || (s == bs && k < bk)) { bs = s; bk = k; }
    }

    // scatter: quantized, loss, dw atomics [d][k], counts
    const float4* er = (const float4*)(g_ET + (size_t)bk * D);
    float4 ea = er[lane * 2], eb = er[lane * 2 + 1];
    float4* qo = (float4*)(out_q + n * D);
    qo[lane * 2] = ea; qo[lane * 2 + 1] = eb;
    float dx0 = ea.x - xa.x, dx1 = ea.y - xa.y, dx2 = ea.z - xa.z, dx3 = ea.w - xa.w;
    float dx4 = eb.x - xb.x, dx5 = eb.y - xb.y, dx6 = eb.z - xb.z, dx7 = eb.w - xb.w;
    float ls = dx0*dx0 + dx1*dx1 + dx2*dx2 + dx3*dx3 + dx4*dx4 + dx5*dx5 + dx6*dx6 + dx7*dx7;

    int d0 = lane * 8;
    atomicAdd(&g_dw[(size_t)(d0 + 0) * K + bk], xa.x);
    atomicAdd(&g_dw[(size_t)(d0 + 1) * K + bk], xa.y);
    atomicAdd(&g_dw[(size_t)(d0 + 2) * K + bk], xa.z);
    atomicAdd(&g_dw[(size_t)(d0 + 3) * K + bk], xa.w);
    atomicAdd(&g_dw[(size_t)(d0 + 4) * K + bk], xb.x);
    atomicAdd(&g_dw[(size_t)(d0 + 5) * K + bk], xb.y);
    atomicAdd(&g_dw[(size_t)(d0 + 6) * K + bk], xb.z);
    atomicAdd(&g_dw[(size_t)(d0 + 7) * K + bk], xb.w);

    #pragma unroll
    for (int o = 16; o; o >>= 1) ls += __shfl_down_sync(0xffffffffu, ls, o);
    if (lane == 0) {
        atomicAdd(&g_loss, ls);
        atomicAdd(&g_counts[bk], 1);
        out_idx[n] = (float)bk;
    }
}

// ================= stats / new embeddings =================
__global__ void k_stats(const float* __restrict__ ema_counter,
                        const float* __restrict__ ema_cluster,
                        float* __restrict__ out) {
    __shared__ float sh[64];
    __shared__ float sh_n;
    int tid = threadIdx.x;
    float counter = ema_counter[0] + 1.0f;
    float bias = 1.0f - powf(DECAY, counter);
    float cavg[4]; float npart = 0.f, epart = 0.f;
    #pragma unroll
    for (int j = 0; j < 4; j++) {
        int k = tid + j * 1024;
        float cnt = (float)g_counts[k];
        float ch = ema_cluster[k] * DECAY + cnt * ONE_MINUS_DECAY;
        float ca = ch / bias;
        cavg[j] = ca; npart += ca;
        float p = cnt * (1.0f / (float)NROWS);
        epart += p * logf(p + 1e-10f);
    }
    #pragma unroll
    for (int o = 16; o; o >>= 1) {
        npart += __shfl_down_sync(0xffffffffu, npart, o);
        epart += __shfl_down_sync(0xffffffffu, epart, o);
    }
    if ((tid & 31) == 0) { sh[tid >> 5] = npart; sh[32 + (tid >> 5)] = epart; }
    __syncthreads();
    if (tid < 32) {
        float a = sh[tid], b = sh[32 + tid];
        #pragma unroll
        for (int o = 16; o; o >>= 1) {
            a += __shfl_down_sync(0xffffffffu, a, o);
            b += __shfl_down_sync(0xffffffffu, b, o);
        }
        if (tid == 0) {
            sh_n = a;
            out[OFF_PERP] = expf(-b);
            float el = g_loss / (float)((size_t)NROWS * D);
            out[OFF_LOSS] = el + COMMIT * el;
            g_bias = bias;
        }
    }
    __syncthreads();
    float n = sh_n;
    #pragma unroll
    for (int j = 0; j < 4; j++) {
        int k = tid + j * 1024;
        g_cnorm[k] = (cavg[j] + EPSV) / (n + (float)K * EPSV) * n;
    }
}

__global__ void k_newemb(const float* __restrict__ ema_dw, float* __restrict__ out_ne) {
    int i = blockIdx.x * 256 + threadIdx.x;
    int k = i & (K - 1);
    float dwh = ema_dw[i] * DECAY + g_dw[i] * ONE_MINUS_DECAY;
    out_ne[i] = (dwh / g_bias) / g_cnorm[k];
}

// ================= launch =================
extern "C" void kernel_launch(void* const* d_in, const int* in_sizes, int n_in,
                              void* d_out, int out_size) {
    const float* x   = (const float*)d_in[0];
    const float* emb = (const float*)d_in[1];
    const float* ctr = (const float*)d_in[2];
    const float* ecl = (const float*)d_in[3];
    const float* edw = (const float*)d_in[4];
    float* out = (float*)d_out;

    cudaFuncSetAttribute(k_argmin, cudaFuncAttributeMaxDynamicSharedMemorySize, SMEM_SZ);

    k_zero<<<1024, 256>>>();
    k_ce<<<K / 256, 256>>>(emb);
    k_transpose<<<dim3(K / 32, D / 32), dim3(32, 8)>>>(emb);
    k_xq<<<((size_t)NROWS * D / 8) / 256, 256>>>(x);
    k_argmin<<<8192, 256, SMEM_SZ>>>();
    k_select<<<NROWS / 8, 256>>>(x, out + OFF_Q, out + OFF_IDX);
    k_stats<<<1, 1024>>>(ctr, ecl, out);
    k_newemb<<<(D * K) / 256, 256>>>(edw, out + OFF_NE);
}

// round 10
// speedup vs baseline: 1.4455x; 1.4455x over previous
#include <cuda_runtime.h>
#include <cuda_fp16.h>
#include <cstdint>

#define NROWS 32768
#define D 256
#define K 4096
#define DECAY 0.99f
#define ONE_MINUS_DECAY 0.01f
#define EPSV 1e-5f
#define COMMIT 0.25f

static const size_t OFF_Q    = 0;
static const size_t OFF_LOSS = 8388608;
static const size_t OFF_PERP = 8388609;
static const size_t OFF_IDX  = 8388610;
static const size_t OFF_NE   = 8421378;

// -------- device scratch --------
__device__ float g_ce[K];
__device__ float g_ET[(size_t)K * D];
__device__ __align__(16) __half g_xh[(size_t)NROWS * D];
__device__ __align__(16) __half g_eh[(size_t)K * D];
__device__ float g_dw[(size_t)D * K];             // [d][k]
__device__ int   g_counts[K];
__device__ float4 g_t2[(size_t)NROWS * 32];       // [row][cg] = {v1, i1, v2, i2}
__device__ float g_loss;
__device__ float g_bias;
__device__ float g_cnorm[K];

// ================= PTX helpers =================
__device__ __forceinline__ uint32_t smem_to_u32(const void* p) {
    uint32_t a;
    asm("{ .reg .u64 t; cvta.to.shared.u64 t, %1; cvt.u32.u64 %0, t; }" : "=r"(a) : "l"(p));
    return a;
}
__device__ __forceinline__ void cp16(uint32_t saddr, const void* g) {
    asm volatile("cp.async.cg.shared.global [%0], [%1], 16;" :: "r"(saddr), "l"(g));
}
#define CP_COMMIT() asm volatile("cp.async.commit_group;" ::: "memory")
#define CP_WAIT2()  asm volatile("cp.async.wait_group 2;" ::: "memory")

#define LDSM4(r0, r1, r2, r3, a) \
    asm volatile("ldmatrix.sync.aligned.m8n8.x4.shared.b16 {%0,%1,%2,%3}, [%4];" \
        : "=r"(r0), "=r"(r1), "=r"(r2), "=r"(r3) : "r"(a))
#define LDSM2(r0, r1, a) \
    asm volatile("ldmatrix.sync.aligned.m8n8.x2.shared.b16 {%0,%1}, [%2];" \
        : "=r"(r0), "=r"(r1) : "r"(a))

__device__ __forceinline__ void mma16816(float* c, const uint32_t* a, const uint32_t* b) {
    asm volatile("mma.sync.aligned.m16n8k16.row.col.f32.f16.f16.f32 "
        "{%0,%1,%2,%3}, {%4,%5,%6,%7}, {%8,%9}, {%0,%1,%2,%3};"
        : "+f"(c[0]), "+f"(c[1]), "+f"(c[2]), "+f"(c[3])
        : "r"(a[0]), "r"(a[1]), "r"(a[2]), "r"(a[3]), "r"(b[0]), "r"(b[1]));
}

__device__ __forceinline__ uint32_t sw128(uint32_t b) { return b ^ ((b >> 3) & 0x70); }
__device__ __forceinline__ bool lt2(float v, int i, float u, int j) {
    return v < u || (v == u && i < j);
}

// ================= small kernels =================
__global__ void k_zero() {
    int i = blockIdx.x * blockDim.x + threadIdx.x, st = gridDim.x * blockDim.x;
    for (int j = i; j < D * K; j += st) g_dw[j] = 0.f;
    for (int j = i; j < K; j += st) g_counts[j] = 0;
    if (i == 0) g_loss = 0.f;
}

__global__ void k_ce(const float* __restrict__ E) {
    int k = blockIdx.x * 256 + threadIdx.x;
    float s = 0.f;
    #pragma unroll 8
    for (int d = 0; d < D; d++) { float v = E[(size_t)d * K + k]; s = fmaf(v, v, s); }
    g_ce[k] = s;
}

// transpose E -> g_ET (fp32) and g_eh (fp16) in one pass
__global__ void k_transpose(const float* __restrict__ E) {
    __shared__ float t[32][33];
    int kb = blockIdx.x * 32, db = blockIdx.y * 32;
    int x = threadIdx.x, y0 = threadIdx.y;
    #pragma unroll
    for (int j = 0; j < 32; j += 8) t[y0 + j][x] = E[(size_t)(db + y0 + j) * K + kb + x];
    __syncthreads();
    #pragma unroll
    for (int j = 0; j < 32; j += 8) {
        float v = t[x][y0 + j];
        size_t o = (size_t)(kb + y0 + j) * D + db + x;
        g_ET[o] = v;
        g_eh[o] = __float2half_rn(v);
    }
}

__global__ void k_xh(const float* __restrict__ X) {
    size_t i = (size_t)blockIdx.x * 256 + threadIdx.x;
    float4 a = *(const float4*)(X + i * 8);
    float4 b = *(const float4*)(X + i * 8 + 4);
    __half h[8] = { __float2half_rn(a.x), __float2half_rn(a.y), __float2half_rn(a.z), __float2half_rn(a.w),
                    __float2half_rn(b.x), __float2half_rn(b.y), __float2half_rn(b.z), __float2half_rn(b.w) };
    *(uint4*)(g_xh + i * 8) = *(uint4*)h;
}

// ================= approx argmin GEMM (HMMA, K=256, top-2 per 128-tile) =================
#define ST_SZ   32768
#define SM_CS   98304
#define SMEM_SZ 98816

__global__ void __launch_bounds__(256, 2)
k_argmin() {
    extern __shared__ char smem[];
    const int tid = threadIdx.x;
    const int wid = tid >> 5, lane = tid & 31;
    const int rt = blockIdx.x >> 5, cg = blockIdx.x & 31;
    const int row0 = rt * 128, kc0 = cg * 128;
    const int wr = wid >> 2, wc = wid & 3;
    const uint32_t sb = smem_to_u32(smem);

    float* cs = (float*)(smem + SM_CS);
    if (tid < 128) cs[tid] = g_ce[kc0 + tid];

    const __half* Ag = g_xh + (size_t)row0 * D;
    const __half* Bg = g_eh + (size_t)kc0 * D;

    float acc[4][4][4];
    #pragma unroll
    for (int mt = 0; mt < 4; mt++)
        #pragma unroll
        for (int nt = 0; nt < 4; nt++)
            #pragma unroll
            for (int j = 0; j < 4; j++) acc[mt][nt][j] = 0.f;

    auto issue = [&](int st) {
        int buf = st - (st / 3) * 3;
        uint32_t abase = sb + (uint32_t)buf * ST_SZ;
        uint32_t bbase = abase + 16384;
        int k0 = st * 64;
        #pragma unroll
        for (int j = 0; j < 4; j++) {
            int chunk = tid + j * 256;
            int r = chunk >> 3, cc = chunk & 7;
            uint32_t so = sw128((uint32_t)(r * 128 + cc * 16));
            cp16(abase + so, Ag + (size_t)r * D + k0 + cc * 8);
            cp16(bbase + so, Bg + (size_t)r * D + k0 + cc * 8);
        }
        CP_COMMIT();
    };

    issue(0); issue(1); issue(2);

    const int l15 = lane & 15;

    #pragma unroll 1
    for (int st = 0; st < 4; st++) {
        CP_WAIT2();
        __syncthreads();
        int buf = st - (st / 3) * 3;
        uint32_t abase = sb + (uint32_t)buf * ST_SZ;
        uint32_t bbase = abase + 16384;

        #pragma unroll
        for (int s = 0; s < 4; s++) {
            uint32_t af[4][4], bf[4][2];
            #pragma unroll
            for (int mt = 0; mt < 4; mt++) {
                uint32_t ro = sw128((uint32_t)((wr * 64 + mt * 16 + l15) * 128 + s * 32 + (lane >> 4) * 16));
                LDSM4(af[mt][0], af[mt][1], af[mt][2], af[mt][3], abase + ro);
            }
            #pragma unroll
            for (int nt = 0; nt < 4; nt++) {
                uint32_t ro = sw128((uint32_t)((wc * 32 + nt * 8 + (l15 & 7)) * 128 + s * 32 + ((l15 >> 3) & 1) * 16));
                LDSM2(bf[nt][0], bf[nt][1], bbase + ro);
            }
            #pragma unroll
            for (int mt = 0; mt < 4; mt++)
                #pragma unroll
                for (int nt = 0; nt < 4; nt++)
                    mma16816(acc[mt][nt], af[mt], bf[nt]);
        }

        __syncthreads();
        if (st + 3 < 4) issue(st + 3);
        else CP_COMMIT();
    }

    // ---- scores -> smem (stride 129 to kill bank conflicts) ----
    float* sc = (float*)smem;
    #pragma unroll
    for (int mt = 0; mt < 4; mt++)
        #pragma unroll
        for (int h = 0; h < 2; h++) {
            int row = wr * 64 + mt * 16 + (lane >> 2) + 8 * h;
            #pragma unroll
            for (int nt = 0; nt < 4; nt++) {
                int col = wc * 32 + nt * 8 + 2 * (lane & 3);
                sc[row * 129 + col]     = cs[col]     - 2.0f * acc[mt][nt][h * 2 + 0];
                sc[row * 129 + col + 1] = cs[col + 1] - 2.0f * acc[mt][nt][h * 2 + 1];
            }
        }
    __syncthreads();

    // ---- per-row top-2 scan (1 thread/row; tie -> smaller index via strict <) ----
    if (tid < 128) {
        float v1 = 3.4e38f, v2 = 3.4e38f; int i1 = 0, i2 = 0;
        #pragma unroll 8
        for (int c = 0; c < 128; c++) {
            float v = sc[tid * 129 + c];
            if (v < v1) { v2 = v1; i2 = i1; v1 = v; i1 = c; }
            else if (v < v2) { v2 = v; i2 = c; }
        }
        g_t2[(size_t)(row0 + tid) * 32 + cg] =
            make_float4(v1, __int_as_float(kc0 + i1), v2, __int_as_float(kc0 + i2));
    }
}

// ================= select (top-4 merge + exact rescore) + scatter =================
__global__ void __launch_bounds__(256)
k_select(const float* __restrict__ X, float* __restrict__ out_q, float* __restrict__ out_idx) {
    const int wid = threadIdx.x >> 5, lane = threadIdx.x & 31;
    const size_t n = (size_t)blockIdx.x * 8 + wid;

    float4 cc = g_t2[n * 32 + lane];
    float t4v[4]; int t4i[4];
    t4v[0] = cc.x; t4i[0] = __float_as_int(cc.y);
    t4v[1] = cc.z; t4i[1] = __float_as_int(cc.w);
    t4v[2] = t4v[3] = 3.4e38f; t4i[2] = t4i[3] = 0x7fffffff;

    #pragma unroll
    for (int o = 1; o < 32; o <<= 1) {
        float rv[4]; int ri[4];
        #pragma unroll
        for (int s = 0; s < 4; s++) {
            rv[s] = __shfl_xor_sync(0xffffffffu, t4v[s], o);
            ri[s] = __shfl_xor_sync(0xffffffffu, t4i[s], o);
        }
        #pragma unroll
        for (int s = 0; s < 4; s++) {
            float v = rv[s]; int i = ri[s];
            if (lt2(v, i, t4v[3], t4i[3])) {
                if (lt2(v, i, t4v[0], t4i[0])) {
                    t4v[3]=t4v[2]; t4i[3]=t4i[2]; t4v[2]=t4v[1]; t4i[2]=t4i[1];
                    t4v[1]=t4v[0]; t4i[1]=t4i[0]; t4v[0]=v; t4i[0]=i;
                } else if (lt2(v, i, t4v[1], t4i[1])) {
                    t4v[3]=t4v[2]; t4i[3]=t4i[2]; t4v[2]=t4v[1]; t4i[2]=t4i[1];
                    t4v[1]=v; t4i[1]=i;
                } else if (lt2(v, i, t4v[2], t4i[2])) {
                    t4v[3]=t4v[2]; t4i[3]=t4i[2]; t4v[2]=v; t4i[2]=i;
                } else {
                    t4v[3]=v; t4i[3]=i;
                }
            }
        }
    }

    // exact fp32 rescore of 4 candidates: hoisted gathers (MLP), ce reused for ||e||^2
    const float4* xr = (const float4*)(X + n * D);
    float4 xa = xr[lane * 2], xb = xr[lane * 2 + 1];
    float4 ea[4], eb[4];
    float cq[4];
    #pragma unroll
    for (int c = 0; c < 4; c++) {
        const float4* er = (const float4*)(g_ET + (size_t)t4i[c] * D);
        ea[c] = er[lane * 2];
        eb[c] = er[lane * 2 + 1];
        cq[c] = g_ce[t4i[c]];
    }
    float bs = 3.4e38f; int bk = 0x7fffffff;
    #pragma unroll
    for (int c = 0; c < 4; c++) {
        float d = xa.x*ea[c].x + xa.y*ea[c].y + xa.z*ea[c].z + xa.w*ea[c].w
                + xb.x*eb[c].x + xb.y*eb[c].y + xb.z*eb[c].z + xb.w*eb[c].w;
        #pragma unroll
        for (int o = 16; o; o >>= 1) d += __shfl_xor_sync(0xffffffffu, d, o);
        float s = cq[c] - 2.0f * d;
        int k = t4i[c];
        if (s < bs || (s == bs && k < bk)) { bs = s; bk = k; }
    }

    // scatter: quantized, loss, dw atomics [d][k], counts
    const float4* er = (const float4*)(g_ET + (size_t)bk * D);
    float4 qa = er[lane * 2], qb = er[lane * 2 + 1];
    float4* qo = (float4*)(out_q + n * D);
    qo[lane * 2] = qa; qo[lane * 2 + 1] = qb;
    float dx0 = qa.x - xa.x, dx1 = qa.y - xa.y, dx2 = qa.z - xa.z, dx3 = qa.w - xa.w;
    float dx4 = qb.x - xb.x, dx5 = qb.y - xb.y, dx6 = qb.z - xb.z, dx7 = qb.w - xb.w;
    float ls = dx0*dx0 + dx1*dx1 + dx2*dx2 + dx3*dx3 + dx4*dx4 + dx5*dx5 + dx6*dx6 + dx7*dx7;

    int d0 = lane * 8;
    atomicAdd(&g_dw[(size_t)(d0 + 0) * K + bk], xa.x);
    atomicAdd(&g_dw[(size_t)(d0 + 1) * K + bk], xa.y);
    atomicAdd(&g_dw[(size_t)(d0 + 2) * K + bk], xa.z);
    atomicAdd(&g_dw[(size_t)(d0 + 3) * K + bk], xa.w);
    atomicAdd(&g_dw[(size_t)(d0 + 4) * K + bk], xb.x);
    atomicAdd(&g_dw[(size_t)(d0 + 5) * K + bk], xb.y);
    atomicAdd(&g_dw[(size_t)(d0 + 6) * K + bk], xb.z);
    atomicAdd(&g_dw[(size_t)(d0 + 7) * K + bk], xb.w);

    #pragma unroll
    for (int o = 16; o; o >>= 1) ls += __shfl_down_sync(0xffffffffu, ls, o);
    if (lane == 0) {
        atomicAdd(&g_loss, ls);
        atomicAdd(&g_counts[bk], 1);
        out_idx[n] = (float)bk;
    }
}

// ================= stats / new embeddings =================
__global__ void k_stats(const float* __restrict__ ema_counter,
                        const float* __restrict__ ema_cluster,
                        float* __restrict__ out) {
    __shared__ float sh[64];
    __shared__ float sh_n;
    int tid = threadIdx.x;
    float counter = ema_counter[0] + 1.0f;
    float bias = 1.0f - powf(DECAY, counter);
    float cavg[4]; float npart = 0.f, epart = 0.f;
    #pragma unroll
    for (int j = 0; j < 4; j++) {
        int k = tid + j * 1024;
        float cnt = (float)g_counts[k];
        float ch = ema_cluster[k] * DECAY + cnt * ONE_MINUS_DECAY;
        float ca = ch / bias;
        cavg[j] = ca; npart += ca;
        float p = cnt * (1.0f / (float)NROWS);
        epart += p * logf(p + 1e-10f);
    }
    #pragma unroll
    for (int o = 16; o; o >>= 1) {
        npart += __shfl_down_sync(0xffffffffu, npart, o);
        epart += __shfl_down_sync(0xffffffffu, epart, o);
    }
    if ((tid & 31) == 0) { sh[tid >> 5] = npart; sh[32 + (tid >> 5)] = epart; }
    __syncthreads();
    if (tid < 32) {
        float a = sh[tid], b = sh[32 + tid];
        #pragma unroll
        for (int o = 16; o; o >>= 1) {
            a += __shfl_down_sync(0xffffffffu, a, o);
            b += __shfl_down_sync(0xffffffffu, b, o);
        }
        if (tid == 0) {
            sh_n = a;
            out[OFF_PERP] = expf(-b);
            float el = g_loss / (float)((size_t)NROWS * D);
            out[OFF_LOSS] = el + COMMIT * el;
            g_bias = bias;
        }
    }
    __syncthreads();
    float n = sh_n;
    #pragma unroll
    for (int j = 0; j < 4; j++) {
        int k = tid + j * 1024;
        g_cnorm[k] = (cavg[j] + EPSV) / (n + (float)K * EPSV) * n;
    }
}

__global__ void k_newemb(const float* __restrict__ ema_dw, float* __restrict__ out_ne) {
    int i = blockIdx.x * 256 + threadIdx.x;
    int k = i & (K - 1);
    float dwh = ema_dw[i] * DECAY + g_dw[i] * ONE_MINUS_DECAY;
    out_ne[i] = (dwh / g_bias) / g_cnorm[k];
}

// ================= launch =================
// NOTE: k_argmin is deliberately the 4th launch — the ncu capture window
// consistently profiles the 4th kernel, and we need k_argmin's profile.
// k_zero only feeds k_select, so moving it after k_argmin is safe.
extern "C" void kernel_launch(void* const* d_in, const int* in_sizes, int n_in,
                              void* d_out, int out_size) {
    const float* x   = (const float*)d_in[0];
    const float* emb = (const float*)d_in[1];
    const float* ctr = (const float*)d_in[2];
    const float* ecl = (const float*)d_in[3];
    const float* edw = (const float*)d_in[4];
    float* out = (float*)d_out;

    cudaFuncSetAttribute(k_argmin, cudaFuncAttributeMaxDynamicSharedMemorySize, SMEM_SZ);

    k_ce<<<K / 256, 256>>>(emb);
    k_transpose<<<dim3(K / 32, D / 32), dim3(32, 8)>>>(emb);
    k_xh<<<((size_t)NROWS * D / 8) / 256, 256>>>(x);
    k_argmin<<<8192, 256, SMEM_SZ>>>();
    k_zero<<<1024, 256>>>();
    k_select<<<NROWS / 8, 256>>>(x, out + OFF_Q, out + OFF_IDX);
    k_stats<<<1, 1024>>>(ctr, ecl, out);
    k_newemb<<<(D * K) / 256, 256>>>(edw, out + OFF_NE);
}